// round 11
// baseline (speedup 1.0000x reference)
// R11: byte-identical resubmission of R10 (two broker container failures with
// no kernel signal; hang-audit clean — R5 precedent says resubmit).
// R10: attn smem 80K->64K by recycling the Q buffer as K/V stage 0 after the
// prologue; __launch_bounds__(128,3) -> 3 CTAs/SM (12 warps). GEMMs unchanged.
#include <cuda_runtime.h>
#include <cuda_bf16.h>
#include <math.h>
#include <stdint.h>

#define B_  4
#define S_  2048
#define D_  1024
#define H_  16
#define DK_ 64
#define M_  (B_ * S_)

// ---------------------------------------------------------------------------
// Scratch
// ---------------------------------------------------------------------------
__device__ __nv_bfloat16 g_xhi [M_ * D_];
__device__ __nv_bfloat16 g_xlo [M_ * D_];
__device__ __nv_bfloat16 g_qhi [M_ * D_];
__device__ __nv_bfloat16 g_qlo [M_ * D_];
__device__ __nv_bfloat16 g_khi [M_ * D_];
__device__ __nv_bfloat16 g_klo [M_ * D_];
__device__ __nv_bfloat16 g_vhi [M_ * D_];
__device__ __nv_bfloat16 g_vlo [M_ * D_];
__device__ __nv_bfloat16 g_aohi[M_ * D_];
__device__ __nv_bfloat16 g_aolo[M_ * D_];
__device__ __nv_bfloat16 g_whi [4][D_ * D_];
__device__ __nv_bfloat16 g_wlo [4][D_ * D_];

// ---------------------------------------------------------------------------
// PTX helpers
// ---------------------------------------------------------------------------
__device__ __forceinline__ uint32_t smem_u32(const void* p) {
    uint32_t a;
    asm("{ .reg .u64 t; cvta.to.shared.u64 t, %1; cvt.u32.u64 %0, t; }" : "=r"(a) : "l"(p));
    return a;
}

#define CP_ASYNC_16(sa, gp) \
    asm volatile("cp.async.cg.shared.global [%0], [%1], 16;" :: "r"(sa), "l"(gp))
#define CP_COMMIT() asm volatile("cp.async.commit_group;" ::: "memory")
template<int N> __device__ __forceinline__ void cp_wait() {
    asm volatile("cp.async.wait_group %0;" :: "n"(N) : "memory");
}

__device__ __forceinline__ void mma16816(float* d, const uint32_t* a, const uint32_t* b) {
    asm volatile("mma.sync.aligned.m16n8k16.row.col.f32.bf16.bf16.f32 "
                 "{%0,%1,%2,%3}, {%4,%5,%6,%7}, {%8,%9}, {%0,%1,%2,%3};"
                 : "+f"(d[0]), "+f"(d[1]), "+f"(d[2]), "+f"(d[3])
                 : "r"(a[0]), "r"(a[1]), "r"(a[2]), "r"(a[3]), "r"(b[0]), "r"(b[1]));
}

// fp32 pair -> bf16x2 hi + exact residual bf16x2 lo. a = even col, b = odd col.
__device__ __forceinline__ void pack_hilo(float a, float b, uint32_t& hi, uint32_t& lo) {
    uint32_t h;
    asm("cvt.rn.bf16x2.f32 %0, %1, %2;" : "=r"(h) : "f"(b), "f"(a));
    float ra = a - __uint_as_float(h << 16);
    float rb = b - __uint_as_float(h & 0xffff0000u);
    uint32_t l;
    asm("cvt.rn.bf16x2.f32 %0, %1, %2;" : "=r"(l) : "f"(rb), "f"(ra));
    hi = h; lo = l;
}

// ----- 64B-row tiles (GEMM, BK=32) -----
__device__ __forceinline__ uint32_t sw_off(int row, int chunk) {
    return (uint32_t)(row * 64 + ((chunk ^ ((row >> 1) & 3)) << 4));
}
__device__ __forceinline__ void ldm_a(uint32_t tile, int row0, int kstep, int lane, uint32_t* r) {
    int row = row0 + (lane & 15);
    int ck  = kstep * 2 + ((lane >> 4) & 1);
    uint32_t addr = tile + sw_off(row, ck);
    asm volatile("ldmatrix.sync.aligned.m8n8.x4.shared.b16 {%0,%1,%2,%3}, [%4];"
                 : "=r"(r[0]), "=r"(r[1]), "=r"(r[2]), "=r"(r[3]) : "r"(addr));
}
__device__ __forceinline__ void ldm_b(uint32_t tile, int row0, int kstep, int lane, uint32_t* r) {
    int row = row0 + (lane & 7) + ((lane & 16) ? 8 : 0);
    int ck  = kstep * 2 + ((lane >> 3) & 1);
    uint32_t addr = tile + sw_off(row, ck);
    asm volatile("ldmatrix.sync.aligned.m8n8.x4.shared.b16 {%0,%1,%2,%3}, [%4];"
                 : "=r"(r[0]), "=r"(r[1]), "=r"(r[2]), "=r"(r[3]) : "r"(addr));
}

// ----- 128B-row tiles (attention, 64x64 bf16) -----
__device__ __forceinline__ uint32_t swoff128(int row, int ck) {
    return (uint32_t)(row * 128 + ((ck ^ (row & 7)) << 4));
}
__device__ __forceinline__ void ldm_a128(uint32_t tile, int row0, int t4, int lane, uint32_t* r) {
    int row = row0 + (lane & 15);
    int ck  = t4 * 2 + ((lane >> 4) & 1);
    uint32_t addr = tile + swoff128(row, ck);
    asm volatile("ldmatrix.sync.aligned.m8n8.x4.shared.b16 {%0,%1,%2,%3}, [%4];"
                 : "=r"(r[0]), "=r"(r[1]), "=r"(r[2]), "=r"(r[3]) : "r"(addr));
}
__device__ __forceinline__ void ldm_b128(uint32_t tile, int n0, int t4, int lane, uint32_t* r) {
    int row = n0 + (lane & 7) + ((lane >> 1) & 8);
    int ck  = t4 * 2 + ((lane >> 3) & 1);
    uint32_t addr = tile + swoff128(row, ck);
    asm volatile("ldmatrix.sync.aligned.m8n8.x4.shared.b16 {%0,%1,%2,%3}, [%4];"
                 : "=r"(r[0]), "=r"(r[1]), "=r"(r[2]), "=r"(r[3]) : "r"(addr));
}
__device__ __forceinline__ void ldm_vt128(uint32_t tile, int k0, int jp, int lane, uint32_t* r) {
    int row = k0 + (lane & 7) + (lane & 8);
    int ck  = jp * 2 + ((lane >> 4) & 1);
    uint32_t addr = tile + swoff128(row, ck);
    asm volatile("ldmatrix.sync.aligned.m8n8.x4.trans.shared.b16 {%0,%1,%2,%3}, [%4];"
                 : "=r"(r[0]), "=r"(r[1]), "=r"(r[2]), "=r"(r[3]) : "r"(addr));
}

// ---------------------------------------------------------------------------
// converts
// ---------------------------------------------------------------------------
__global__ __launch_bounds__(256) void f32_to_hilo(const float* __restrict__ in,
                                                   __nv_bfloat16* __restrict__ hi,
                                                   __nv_bfloat16* __restrict__ lo,
                                                   int n2)
{
    int i = blockIdx.x * blockDim.x + threadIdx.x;
    if (i >= n2) return;
    float2 v = ((const float2*)in)[i];
    uint32_t h, l;
    pack_hilo(v.x, v.y, h, l);
    ((uint32_t*)hi)[i] = h;
    ((uint32_t*)lo)[i] = l;
}

__global__ __launch_bounds__(256) void w4_to_hilo(const float* __restrict__ w0,
                                                  const float* __restrict__ w1,
                                                  const float* __restrict__ w2,
                                                  const float* __restrict__ w3,
                                                  __nv_bfloat16* __restrict__ hi,
                                                  __nv_bfloat16* __restrict__ lo)
{
    const int n2 = D_ * D_ / 2;
    int i = blockIdx.x * blockDim.x + threadIdx.x;
    if (i >= n2) return;
    const int which = blockIdx.y;
    const float* src = (which == 0) ? w0 : (which == 1) ? w1 : (which == 2) ? w2 : w3;
    float2 v = ((const float2*)src)[i];
    uint32_t h, l;
    pack_hilo(v.x, v.y, h, l);
    ((uint32_t*)(hi + (size_t)which * (D_ * D_)))[i] = h;
    ((uint32_t*)(lo + (size_t)which * (D_ * D_)))[i] = l;
}

// ---------------------------------------------------------------------------
// Shared GEMM mainloop — 3-stage cp.async, ONE barrier per chunk (R9)
// ---------------------------------------------------------------------------
#define STAGE_B   32768
#define GEMM_SMEM (3 * STAGE_B)
#define NCHUNK    32

__device__ __forceinline__ void gemm_mainloop(
    const __nv_bfloat16* __restrict__ Ahi, const __nv_bfloat16* __restrict__ Alo,
    const __nv_bfloat16* __restrict__ Bhi, const __nv_bfloat16* __restrict__ Blo,
    uint32_t sb, int bm, int bn, int t, int lane, int wm, int wn,
    float d[4][4][4])
{
    const int r0 = t >> 2,         c0 = t & 3;
    const int r1 = (t + 256) >> 2, c1 = t & 3;

    auto load_chunk = [&](int chunk, int st) {
        const size_t kb = (size_t)chunk * 32;
        const uint32_t s = sb + (uint32_t)st * STAGE_B;
        {
            uint32_t so = sw_off(r0, c0);
            const size_t ga = (size_t)(bm + r0) * D_ + kb + c0 * 8;
            const size_t gb = (size_t)(bn + r0) * D_ + kb + c0 * 8;
            CP_ASYNC_16(s + so,         Ahi + ga);
            CP_ASYNC_16(s + 8192  + so, Alo + ga);
            CP_ASYNC_16(s + 16384 + so, Bhi + gb);
            CP_ASYNC_16(s + 24576 + so, Blo + gb);
        }
        {
            uint32_t so = sw_off(r1, c1);
            const size_t ga = (size_t)(bm + r1) * D_ + kb + c1 * 8;
            const size_t gb = (size_t)(bn + r1) * D_ + kb + c1 * 8;
            CP_ASYNC_16(s + so,         Ahi + ga);
            CP_ASYNC_16(s + 8192  + so, Alo + ga);
            CP_ASYNC_16(s + 16384 + so, Bhi + gb);
            CP_ASYNC_16(s + 24576 + so, Blo + gb);
        }
        CP_COMMIT();
    };

    load_chunk(0, 0);
    load_chunk(1, 1);

    for (int chunk = 0; chunk < NCHUNK; chunk++) {
        if (chunk + 2 < NCHUNK) cp_wait<1>();
        else                    cp_wait<0>();
        __syncthreads();
        if (chunk + 2 < NCHUNK) load_chunk(chunk + 2, (chunk + 2) % 3);

        const uint32_t tAh = sb + (uint32_t)(chunk % 3) * STAGE_B;
        const uint32_t tAl = tAh + 8192;
        const uint32_t tBh = tAh + 16384;
        const uint32_t tBl = tAh + 24576;

#pragma unroll
        for (int ks = 0; ks < 2; ks++) {
            uint32_t ah[4][4], al[4][4];
#pragma unroll
            for (int i = 0; i < 4; i++) {
                ldm_a(tAh, wm + i * 16, ks, lane, ah[i]);
                ldm_a(tAl, wm + i * 16, ks, lane, al[i]);
            }
            uint32_t bh[2][4], bl[2][4];
#pragma unroll
            for (int jp = 0; jp < 2; jp++) {
                ldm_b(tBh, wn + jp * 16, ks, lane, bh[jp]);
                ldm_b(tBl, wn + jp * 16, ks, lane, bl[jp]);
            }
#pragma unroll
            for (int i = 0; i < 4; i++)
#pragma unroll
                for (int j = 0; j < 4; j++) {
                    const uint32_t* ph = &bh[j >> 1][(j & 1) * 2];
                    const uint32_t* pl = &bl[j >> 1][(j & 1) * 2];
                    mma16816(d[i][j], ah[i], ph);
                    mma16816(d[i][j], ah[i], pl);
                    mma16816(d[i][j], al[i], ph);
                }
        }
    }
}

// ---------------------------------------------------------------------------
// Fused QKV projection
// ---------------------------------------------------------------------------
__global__ __launch_bounds__(256) void gemm_qkv(
    const __nv_bfloat16* __restrict__ Ahi, const __nv_bfloat16* __restrict__ Alo,
    const __nv_bfloat16* __restrict__ Whi, const __nv_bfloat16* __restrict__ Wlo,
    __nv_bfloat16* __restrict__ Qhi, __nv_bfloat16* __restrict__ Qlo,
    __nv_bfloat16* __restrict__ Khi, __nv_bfloat16* __restrict__ Klo,
    __nv_bfloat16* __restrict__ Vhi, __nv_bfloat16* __restrict__ Vlo)
{
    extern __shared__ __align__(1024) char smem[];
    const uint32_t sb = smem_u32(smem);

    const int t     = threadIdx.x;
    const int lane  = t & 31;
    const int w     = t >> 5;
    const int wm    = (w >> 2) * 64;
    const int wn    = (w & 3) * 32;
    const int which = blockIdx.x >> 3;
    const int bn    = (blockIdx.x & 7) * 128;
    const int bm    = blockIdx.y * 128;

    const __nv_bfloat16* Bhi = Whi + (size_t)which * (D_ * D_);
    const __nv_bfloat16* Blo = Wlo + (size_t)which * (D_ * D_);
    __nv_bfloat16* Chi = (which == 0) ? Qhi : (which == 1) ? Khi : Vhi;
    __nv_bfloat16* Clo = (which == 0) ? Qlo : (which == 1) ? Klo : Vlo;
    const float scale = (which == 0) ? 0.125f : 1.0f;

    float d[4][4][4];
#pragma unroll
    for (int i = 0; i < 4; i++)
#pragma unroll
        for (int j = 0; j < 4; j++)
#pragma unroll
            for (int e = 0; e < 4; e++) d[i][j][e] = 0.0f;

    gemm_mainloop(Ahi, Alo, Bhi, Blo, sb, bm, bn, t, lane, wm, wn, d);

#pragma unroll
    for (int i = 0; i < 4; i++) {
        const int row = bm + wm + i * 16 + (lane >> 2);
#pragma unroll
        for (int j = 0; j < 4; j++) {
            const int col = bn + wn + j * 8 + (lane & 3) * 2;
            uint32_t h01, l01, h23, l23;
            pack_hilo(d[i][j][0] * scale, d[i][j][1] * scale, h01, l01);
            pack_hilo(d[i][j][2] * scale, d[i][j][3] * scale, h23, l23);
            *(uint32_t*)(Chi + (size_t)row * D_ + col)       = h01;
            *(uint32_t*)(Clo + (size_t)row * D_ + col)       = l01;
            *(uint32_t*)(Chi + (size_t)(row + 8) * D_ + col) = h23;
            *(uint32_t*)(Clo + (size_t)(row + 8) * D_ + col) = l23;
        }
    }
}

// ---------------------------------------------------------------------------
// O-projection GEMM (fp32 output)
// ---------------------------------------------------------------------------
__global__ __launch_bounds__(256) void gemm_out(
    const __nv_bfloat16* __restrict__ Ahi, const __nv_bfloat16* __restrict__ Alo,
    const __nv_bfloat16* __restrict__ Bhi, const __nv_bfloat16* __restrict__ Blo,
    float* __restrict__ C)
{
    extern __shared__ __align__(1024) char smem[];
    const uint32_t sb = smem_u32(smem);

    const int t    = threadIdx.x;
    const int lane = t & 31;
    const int w    = t >> 5;
    const int wm   = (w >> 2) * 64;
    const int wn   = (w & 3) * 32;
    const int bm   = blockIdx.y * 128;
    const int bn   = blockIdx.x * 128;

    float d[4][4][4];
#pragma unroll
    for (int i = 0; i < 4; i++)
#pragma unroll
        for (int j = 0; j < 4; j++)
#pragma unroll
            for (int e = 0; e < 4; e++) d[i][j][e] = 0.0f;

    gemm_mainloop(Ahi, Alo, Bhi, Blo, sb, bm, bn, t, lane, wm, wn, d);

#pragma unroll
    for (int i = 0; i < 4; i++) {
        const int row = bm + wm + i * 16 + (lane >> 2);
#pragma unroll
        for (int j = 0; j < 4; j++) {
            const int col = bn + wn + j * 8 + (lane & 3) * 2;
            *(float2*)(C + (size_t)row * D_ + col)       = make_float2(d[i][j][0], d[i][j][1]);
            *(float2*)(C + (size_t)(row + 8) * D_ + col) = make_float2(d[i][j][2], d[i][j][3]);
        }
    }
}

// ---------------------------------------------------------------------------
// Flash attention — q64, 64KB smem (Q recycled into stage 0), 3 CTAs/SM.
// Stage s (s=0,1) at sb + s*32768: {Khi, Klo, Vhi, Vlo} 8KB each.
// Q loaded into stage0 during prologue, fragments extracted, then recycled.
// kv(kt) lives in stage (kt+1)&1.
// ---------------------------------------------------------------------------
#define ATT_SMEM 65536

__global__ __launch_bounds__(128, 3) void attn_mma(
    const __nv_bfloat16* __restrict__ Qhi, const __nv_bfloat16* __restrict__ Qlo,
    const __nv_bfloat16* __restrict__ Khi, const __nv_bfloat16* __restrict__ Klo,
    const __nv_bfloat16* __restrict__ Vhi, const __nv_bfloat16* __restrict__ Vlo,
    __nv_bfloat16* __restrict__ AOhi, __nv_bfloat16* __restrict__ AOlo)
{
    extern __shared__ __align__(1024) char smem[];
    const uint32_t sb = smem_u32(smem);
    const int qt   = (int)gridDim.x - 1 - (int)blockIdx.x;
    const int h    = blockIdx.y;
    const int b    = blockIdx.z;
    const int tid  = threadIdx.x;
    const int lane = tid & 31;
    const int w    = tid >> 5;

    const size_t rowbase = (size_t)b * S_;
    const size_t cb      = (size_t)h * DK_;
    const int    q0      = qt * 64;

    // Q -> stage0 (Qhi at +0, Qlo at +8192); kv0 -> stage1 (concurrent)
#pragma unroll
    for (int i = 0; i < 4; i++) {
        int p = tid + 128 * i; int r = p >> 3, ck = p & 7;
        size_t g = (rowbase + q0 + r) * D_ + cb + ck * 8;
        uint32_t so = swoff128(r, ck);
        CP_ASYNC_16(sb + so,        Qhi + g);
        CP_ASYNC_16(sb + 8192 + so, Qlo + g);
    }
    CP_COMMIT();

    auto load_kv = [&](int kt, int st) {
        uint32_t s = sb + (uint32_t)st * 32768;
#pragma unroll
        for (int i = 0; i < 4; i++) {
            int p = tid + 128 * i; int r = p >> 3, ck = p & 7;
            uint32_t so = swoff128(r, ck);
            size_t g = (rowbase + kt * 64 + r) * D_ + cb + ck * 8;
            CP_ASYNC_16(s + so,         Khi + g);
            CP_ASYNC_16(s + 8192  + so, Klo + g);
            CP_ASYNC_16(s + 16384 + so, Vhi + g);
            CP_ASYNC_16(s + 24576 + so, Vlo + g);
        }
        CP_COMMIT();
    };
    load_kv(0, 1);

    cp_wait<1>();          // Q group complete (kv0 may be in flight)
    __syncthreads();

    uint32_t qh[4][4], ql[4][4];
#pragma unroll
    for (int t4 = 0; t4 < 4; t4++) {
        ldm_a128(sb,        w * 16, t4, lane, qh[t4]);
        ldm_a128(sb + 8192, w * 16, t4, lane, ql[t4]);
    }
    __syncthreads();       // all warps done reading Q before stage0 is reused

    float o[8][4];
#pragma unroll
    for (int j = 0; j < 8; j++)
#pragma unroll
        for (int e = 0; e < 4; e++) o[j][e] = 0.0f;
    float miA = -INFINITY, miB = -INFINITY, liA = 0.0f, liB = 0.0f;

    const int rA = w * 16 + (lane >> 2);
    const int cl = 2 * (lane & 3);

    for (int kt = 0; kt <= qt; kt++) {
        // kv(kt) is in stage (kt+1)&1; prefetch kv(kt+1) into (kt)&1
        if (kt < qt) { load_kv(kt + 1, kt & 1); cp_wait<1>(); }
        else         { cp_wait<0>(); }
        __syncthreads();

        const uint32_t Kh = sb + (uint32_t)((kt + 1) & 1) * 32768;
        const uint32_t Kl = Kh + 8192, Vh = Kh + 16384, Vl = Kh + 24576;

        float s[8][4];
#pragma unroll
        for (int j = 0; j < 8; j++)
#pragma unroll
            for (int e = 0; e < 4; e++) s[j][e] = 0.0f;

#pragma unroll
        for (int t4 = 0; t4 < 4; t4++) {
#pragma unroll
            for (int jp = 0; jp < 4; jp++) {
                uint32_t kh[4], kl[4];
                ldm_b128(Kh, jp * 16, t4, lane, kh);
                ldm_b128(Kl, jp * 16, t4, lane, kl);
                mma16816(s[2 * jp],     qh[t4], kh);
                mma16816(s[2 * jp],     qh[t4], kl);
                mma16816(s[2 * jp],     ql[t4], kh);
                mma16816(s[2 * jp + 1], qh[t4], kh + 2);
                mma16816(s[2 * jp + 1], qh[t4], kl + 2);
                mma16816(s[2 * jp + 1], ql[t4], kh + 2);
            }
        }

        if (kt == qt) {
#pragma unroll
            for (int j = 0; j < 8; j++) {
                int c = 8 * j + cl;
                if (c     > rA)     s[j][0] = -INFINITY;
                if (c + 1 > rA)     s[j][1] = -INFINITY;
                if (c     > rA + 8) s[j][2] = -INFINITY;
                if (c + 1 > rA + 8) s[j][3] = -INFINITY;
            }
        }

        float mxA = s[0][0], mxB = s[0][2];
#pragma unroll
        for (int j = 0; j < 8; j++) {
            mxA = fmaxf(mxA, fmaxf(s[j][0], s[j][1]));
            mxB = fmaxf(mxB, fmaxf(s[j][2], s[j][3]));
        }
        mxA = fmaxf(mxA, __shfl_xor_sync(0xffffffffu, mxA, 1));
        mxA = fmaxf(mxA, __shfl_xor_sync(0xffffffffu, mxA, 2));
        mxB = fmaxf(mxB, __shfl_xor_sync(0xffffffffu, mxB, 1));
        mxB = fmaxf(mxB, __shfl_xor_sync(0xffffffffu, mxB, 2));

        float nA = fmaxf(miA, mxA), nB = fmaxf(miB, mxB);
        float aA = __expf(miA - nA), aB = __expf(miB - nB);
        miA = nA; miB = nB;
        liA *= aA; liB *= aB;
#pragma unroll
        for (int j = 0; j < 8; j++) {
            s[j][0] = __expf(s[j][0] - miA);
            s[j][1] = __expf(s[j][1] - miA);
            s[j][2] = __expf(s[j][2] - miB);
            s[j][3] = __expf(s[j][3] - miB);
            liA += s[j][0] + s[j][1];
            liB += s[j][2] + s[j][3];
            o[j][0] *= aA; o[j][1] *= aA; o[j][2] *= aB; o[j][3] *= aB;
        }

        uint32_t ph[4][4], pl[4][4];
#pragma unroll
        for (int t4 = 0; t4 < 4; t4++) {
            pack_hilo(s[2 * t4][0],     s[2 * t4][1],     ph[t4][0], pl[t4][0]);
            pack_hilo(s[2 * t4][2],     s[2 * t4][3],     ph[t4][1], pl[t4][1]);
            pack_hilo(s[2 * t4 + 1][0], s[2 * t4 + 1][1], ph[t4][2], pl[t4][2]);
            pack_hilo(s[2 * t4 + 1][2], s[2 * t4 + 1][3], ph[t4][3], pl[t4][3]);
        }

#pragma unroll
        for (int t4 = 0; t4 < 4; t4++) {
#pragma unroll
            for (int jp = 0; jp < 4; jp++) {
                uint32_t vh[4], vl[4];
                ldm_vt128(Vh, t4 * 16, jp, lane, vh);
                ldm_vt128(Vl, t4 * 16, jp, lane, vl);
                mma16816(o[2 * jp],     ph[t4], vh);
                mma16816(o[2 * jp],     pl[t4], vh);
                mma16816(o[2 * jp],     ph[t4], vl);
                mma16816(o[2 * jp + 1], ph[t4], vh + 2);
                mma16816(o[2 * jp + 1], pl[t4], vh + 2);
                mma16816(o[2 * jp + 1], ph[t4], vl + 2);
            }
        }
        __syncthreads();   // stage fully consumed before it is refilled
    }

    liA += __shfl_xor_sync(0xffffffffu, liA, 1);
    liA += __shfl_xor_sync(0xffffffffu, liA, 2);
    liB += __shfl_xor_sync(0xffffffffu, liB, 1);
    liB += __shfl_xor_sync(0xffffffffu, liB, 2);
    const float invA = 1.0f / liA, invB = 1.0f / liB;

    const size_t gA = (rowbase + q0 + rA) * D_ + cb + cl;
#pragma unroll
    for (int j = 0; j < 8; j++) {
        uint32_t hA, lA, hB, lB;
        pack_hilo(o[j][0] * invA, o[j][1] * invA, hA, lA);
        pack_hilo(o[j][2] * invB, o[j][3] * invB, hB, lB);
        *(uint32_t*)(AOhi + gA + 8 * j)           = hA;
        *(uint32_t*)(AOlo + gA + 8 * j)           = lA;
        *(uint32_t*)(AOhi + gA + 8 * j + 8 * D_)  = hB;
        *(uint32_t*)(AOlo + gA + 8 * j + 8 * D_)  = lB;
    }
}

// ---------------------------------------------------------------------------
// kernel_launch
// ---------------------------------------------------------------------------
extern "C" void kernel_launch(void* const* d_in, const int* in_sizes, int n_in,
                              void* d_out, int out_size)
{
    const float* x  = (const float*)d_in[0];
    const float* wp[4] = { (const float*)d_in[1], (const float*)d_in[2],
                           (const float*)d_in[3], (const float*)d_in[4] };
    float* out = (float*)d_out;

    __nv_bfloat16 *xhi, *xlo, *qhi, *qlo, *khi, *klo, *vhi, *vlo, *aohi, *aolo, *whi, *wlo;
    cudaGetSymbolAddress((void**)&xhi,  g_xhi);
    cudaGetSymbolAddress((void**)&xlo,  g_xlo);
    cudaGetSymbolAddress((void**)&qhi,  g_qhi);
    cudaGetSymbolAddress((void**)&qlo,  g_qlo);
    cudaGetSymbolAddress((void**)&khi,  g_khi);
    cudaGetSymbolAddress((void**)&klo,  g_klo);
    cudaGetSymbolAddress((void**)&vhi,  g_vhi);
    cudaGetSymbolAddress((void**)&vlo,  g_vlo);
    cudaGetSymbolAddress((void**)&aohi, g_aohi);
    cudaGetSymbolAddress((void**)&aolo, g_aolo);
    cudaGetSymbolAddress((void**)&whi,  g_whi);
    cudaGetSymbolAddress((void**)&wlo,  g_wlo);

    const int n2x = M_ * D_ / 2;
    const int n2w = D_ * D_ / 2;
    f32_to_hilo<<<(n2x + 255) / 256, 256>>>(x, xhi, xlo, n2x);
    w4_to_hilo<<<dim3((n2w + 255) / 256, 4), 256>>>(wp[0], wp[1], wp[2], wp[3], whi, wlo);

    cudaFuncSetAttribute(gemm_qkv, cudaFuncAttributeMaxDynamicSharedMemorySize, GEMM_SMEM);
    cudaFuncSetAttribute(gemm_out, cudaFuncAttributeMaxDynamicSharedMemorySize, GEMM_SMEM);
    cudaFuncSetAttribute(attn_mma, cudaFuncAttributeMaxDynamicSharedMemorySize, ATT_SMEM);

    gemm_qkv<<<dim3(24, M_ / 128), 256, GEMM_SMEM>>>(xhi, xlo, whi, wlo,
                                                     qhi, qlo, khi, klo, vhi, vlo);

    attn_mma<<<dim3(S_ / 64, H_, B_), 128, ATT_SMEM>>>(qhi, qlo, khi, klo, vhi, vlo, aohi, aolo);

    gemm_out<<<dim3(D_ / 128, M_ / 128), 256, GEMM_SMEM>>>(
        aohi, aolo, whi + 3 * (size_t)(D_ * D_), wlo + 3 * (size_t)(D_ * D_), out);
}

// round 14
// speedup vs baseline: 1.1476x; 1.1476x over previous
// R14: third submission of the R12 source (broker "container failed twice" on
// R12 and R13; audit clean — acquisition-level failure signature, not kernel).
// R12: PV path -> fp16 single-product (P cvt f32->f16x2, V stored fp16 by the
// QKV epilogue). QK stays bf16x3. attn stage 32K->24K (smem 48K, 3 CTAs/SM).
#include <cuda_runtime.h>
#include <cuda_bf16.h>
#include <math.h>
#include <stdint.h>

#define B_  4
#define S_  2048
#define D_  1024
#define H_  16
#define DK_ 64
#define M_  (B_ * S_)

// ---------------------------------------------------------------------------
// Scratch (g_vhi holds fp16 payload; type is just 16-bit storage)
// ---------------------------------------------------------------------------
__device__ __nv_bfloat16 g_xhi [M_ * D_];
__device__ __nv_bfloat16 g_xlo [M_ * D_];
__device__ __nv_bfloat16 g_qhi [M_ * D_];
__device__ __nv_bfloat16 g_qlo [M_ * D_];
__device__ __nv_bfloat16 g_khi [M_ * D_];
__device__ __nv_bfloat16 g_klo [M_ * D_];
__device__ __nv_bfloat16 g_vhi [M_ * D_];
__device__ __nv_bfloat16 g_aohi[M_ * D_];
__device__ __nv_bfloat16 g_aolo[M_ * D_];
__device__ __nv_bfloat16 g_whi [4][D_ * D_];
__device__ __nv_bfloat16 g_wlo [4][D_ * D_];

// ---------------------------------------------------------------------------
// PTX helpers
// ---------------------------------------------------------------------------
__device__ __forceinline__ uint32_t smem_u32(const void* p) {
    uint32_t a;
    asm("{ .reg .u64 t; cvta.to.shared.u64 t, %1; cvt.u32.u64 %0, t; }" : "=r"(a) : "l"(p));
    return a;
}

#define CP_ASYNC_16(sa, gp) \
    asm volatile("cp.async.cg.shared.global [%0], [%1], 16;" :: "r"(sa), "l"(gp))
#define CP_COMMIT() asm volatile("cp.async.commit_group;" ::: "memory")
template<int N> __device__ __forceinline__ void cp_wait() {
    asm volatile("cp.async.wait_group %0;" :: "n"(N) : "memory");
}

__device__ __forceinline__ void mma16816(float* d, const uint32_t* a, const uint32_t* b) {
    asm volatile("mma.sync.aligned.m16n8k16.row.col.f32.bf16.bf16.f32 "
                 "{%0,%1,%2,%3}, {%4,%5,%6,%7}, {%8,%9}, {%0,%1,%2,%3};"
                 : "+f"(d[0]), "+f"(d[1]), "+f"(d[2]), "+f"(d[3])
                 : "r"(a[0]), "r"(a[1]), "r"(a[2]), "r"(a[3]), "r"(b[0]), "r"(b[1]));
}
__device__ __forceinline__ void mma16816f16(float* d, const uint32_t* a, const uint32_t* b) {
    asm volatile("mma.sync.aligned.m16n8k16.row.col.f32.f16.f16.f32 "
                 "{%0,%1,%2,%3}, {%4,%5,%6,%7}, {%8,%9}, {%0,%1,%2,%3};"
                 : "+f"(d[0]), "+f"(d[1]), "+f"(d[2]), "+f"(d[3])
                 : "r"(a[0]), "r"(a[1]), "r"(a[2]), "r"(a[3]), "r"(b[0]), "r"(b[1]));
}

// fp32 pair -> bf16x2 hi + exact residual bf16x2 lo. a = even col, b = odd col.
__device__ __forceinline__ void pack_hilo(float a, float b, uint32_t& hi, uint32_t& lo) {
    uint32_t h;
    asm("cvt.rn.bf16x2.f32 %0, %1, %2;" : "=r"(h) : "f"(b), "f"(a));
    float ra = a - __uint_as_float(h << 16);
    float rb = b - __uint_as_float(h & 0xffff0000u);
    uint32_t l;
    asm("cvt.rn.bf16x2.f32 %0, %1, %2;" : "=r"(l) : "f"(rb), "f"(ra));
    hi = h; lo = l;
}
// fp32 pair -> f16x2 (a low, b high)
__device__ __forceinline__ uint32_t pack_f16x2(float a, float b) {
    uint32_t h;
    asm("cvt.rn.f16x2.f32 %0, %1, %2;" : "=r"(h) : "f"(b), "f"(a));
    return h;
}

// ----- 64B-row tiles (GEMM, BK=32) -----
__device__ __forceinline__ uint32_t sw_off(int row, int chunk) {
    return (uint32_t)(row * 64 + ((chunk ^ ((row >> 1) & 3)) << 4));
}
__device__ __forceinline__ void ldm_a(uint32_t tile, int row0, int kstep, int lane, uint32_t* r) {
    int row = row0 + (lane & 15);
    int ck  = kstep * 2 + ((lane >> 4) & 1);
    uint32_t addr = tile + sw_off(row, ck);
    asm volatile("ldmatrix.sync.aligned.m8n8.x4.shared.b16 {%0,%1,%2,%3}, [%4];"
                 : "=r"(r[0]), "=r"(r[1]), "=r"(r[2]), "=r"(r[3]) : "r"(addr));
}
__device__ __forceinline__ void ldm_b(uint32_t tile, int row0, int kstep, int lane, uint32_t* r) {
    int row = row0 + (lane & 7) + ((lane & 16) ? 8 : 0);
    int ck  = kstep * 2 + ((lane >> 3) & 1);
    uint32_t addr = tile + sw_off(row, ck);
    asm volatile("ldmatrix.sync.aligned.m8n8.x4.shared.b16 {%0,%1,%2,%3}, [%4];"
                 : "=r"(r[0]), "=r"(r[1]), "=r"(r[2]), "=r"(r[3]) : "r"(addr));
}

// ----- 128B-row tiles (attention, 64x64 16-bit) -----
__device__ __forceinline__ uint32_t swoff128(int row, int ck) {
    return (uint32_t)(row * 128 + ((ck ^ (row & 7)) << 4));
}
__device__ __forceinline__ void ldm_a128(uint32_t tile, int row0, int t4, int lane, uint32_t* r) {
    int row = row0 + (lane & 15);
    int ck  = t4 * 2 + ((lane >> 4) & 1);
    uint32_t addr = tile + swoff128(row, ck);
    asm volatile("ldmatrix.sync.aligned.m8n8.x4.shared.b16 {%0,%1,%2,%3}, [%4];"
                 : "=r"(r[0]), "=r"(r[1]), "=r"(r[2]), "=r"(r[3]) : "r"(addr));
}
__device__ __forceinline__ void ldm_b128(uint32_t tile, int n0, int t4, int lane, uint32_t* r) {
    int row = n0 + (lane & 7) + ((lane >> 1) & 8);
    int ck  = t4 * 2 + ((lane >> 3) & 1);
    uint32_t addr = tile + swoff128(row, ck);
    asm volatile("ldmatrix.sync.aligned.m8n8.x4.shared.b16 {%0,%1,%2,%3}, [%4];"
                 : "=r"(r[0]), "=r"(r[1]), "=r"(r[2]), "=r"(r[3]) : "r"(addr));
}
__device__ __forceinline__ void ldm_vt128(uint32_t tile, int k0, int jp, int lane, uint32_t* r) {
    int row = k0 + (lane & 7) + (lane & 8);
    int ck  = jp * 2 + ((lane >> 4) & 1);
    uint32_t addr = tile + swoff128(row, ck);
    asm volatile("ldmatrix.sync.aligned.m8n8.x4.trans.shared.b16 {%0,%1,%2,%3}, [%4];"
                 : "=r"(r[0]), "=r"(r[1]), "=r"(r[2]), "=r"(r[3]) : "r"(addr));
}

// ---------------------------------------------------------------------------
// converts
// ---------------------------------------------------------------------------
__global__ __launch_bounds__(256) void f32_to_hilo(const float* __restrict__ in,
                                                   __nv_bfloat16* __restrict__ hi,
                                                   __nv_bfloat16* __restrict__ lo,
                                                   int n2)
{
    int i = blockIdx.x * blockDim.x + threadIdx.x;
    if (i >= n2) return;
    float2 v = ((const float2*)in)[i];
    uint32_t h, l;
    pack_hilo(v.x, v.y, h, l);
    ((uint32_t*)hi)[i] = h;
    ((uint32_t*)lo)[i] = l;
}

__global__ __launch_bounds__(256) void w4_to_hilo(const float* __restrict__ w0,
                                                  const float* __restrict__ w1,
                                                  const float* __restrict__ w2,
                                                  const float* __restrict__ w3,
                                                  __nv_bfloat16* __restrict__ hi,
                                                  __nv_bfloat16* __restrict__ lo)
{
    const int n2 = D_ * D_ / 2;
    int i = blockIdx.x * blockDim.x + threadIdx.x;
    if (i >= n2) return;
    const int which = blockIdx.y;
    const float* src = (which == 0) ? w0 : (which == 1) ? w1 : (which == 2) ? w2 : w3;
    float2 v = ((const float2*)src)[i];
    uint32_t h, l;
    pack_hilo(v.x, v.y, h, l);
    ((uint32_t*)(hi + (size_t)which * (D_ * D_)))[i] = h;
    ((uint32_t*)(lo + (size_t)which * (D_ * D_)))[i] = l;
}

// ---------------------------------------------------------------------------
// Shared GEMM mainloop — 3-stage cp.async, ONE barrier per chunk (R9)
// ---------------------------------------------------------------------------
#define STAGE_B   32768
#define GEMM_SMEM (3 * STAGE_B)
#define NCHUNK    32

__device__ __forceinline__ void gemm_mainloop(
    const __nv_bfloat16* __restrict__ Ahi, const __nv_bfloat16* __restrict__ Alo,
    const __nv_bfloat16* __restrict__ Bhi, const __nv_bfloat16* __restrict__ Blo,
    uint32_t sb, int bm, int bn, int t, int lane, int wm, int wn,
    float d[4][4][4])
{
    const int r0 = t >> 2,         c0 = t & 3;
    const int r1 = (t + 256) >> 2, c1 = t & 3;

    auto load_chunk = [&](int chunk, int st) {
        const size_t kb = (size_t)chunk * 32;
        const uint32_t s = sb + (uint32_t)st * STAGE_B;
        {
            uint32_t so = sw_off(r0, c0);
            const size_t ga = (size_t)(bm + r0) * D_ + kb + c0 * 8;
            const size_t gb = (size_t)(bn + r0) * D_ + kb + c0 * 8;
            CP_ASYNC_16(s + so,         Ahi + ga);
            CP_ASYNC_16(s + 8192  + so, Alo + ga);
            CP_ASYNC_16(s + 16384 + so, Bhi + gb);
            CP_ASYNC_16(s + 24576 + so, Blo + gb);
        }
        {
            uint32_t so = sw_off(r1, c1);
            const size_t ga = (size_t)(bm + r1) * D_ + kb + c1 * 8;
            const size_t gb = (size_t)(bn + r1) * D_ + kb + c1 * 8;
            CP_ASYNC_16(s + so,         Ahi + ga);
            CP_ASYNC_16(s + 8192  + so, Alo + ga);
            CP_ASYNC_16(s + 16384 + so, Bhi + gb);
            CP_ASYNC_16(s + 24576 + so, Blo + gb);
        }
        CP_COMMIT();
    };

    load_chunk(0, 0);
    load_chunk(1, 1);

    for (int chunk = 0; chunk < NCHUNK; chunk++) {
        if (chunk + 2 < NCHUNK) cp_wait<1>();
        else                    cp_wait<0>();
        __syncthreads();
        if (chunk + 2 < NCHUNK) load_chunk(chunk + 2, (chunk + 2) % 3);

        const uint32_t tAh = sb + (uint32_t)(chunk % 3) * STAGE_B;
        const uint32_t tAl = tAh + 8192;
        const uint32_t tBh = tAh + 16384;
        const uint32_t tBl = tAh + 24576;

#pragma unroll
        for (int ks = 0; ks < 2; ks++) {
            uint32_t ah[4][4], al[4][4];
#pragma unroll
            for (int i = 0; i < 4; i++) {
                ldm_a(tAh, wm + i * 16, ks, lane, ah[i]);
                ldm_a(tAl, wm + i * 16, ks, lane, al[i]);
            }
            uint32_t bh[2][4], bl[2][4];
#pragma unroll
            for (int jp = 0; jp < 2; jp++) {
                ldm_b(tBh, wn + jp * 16, ks, lane, bh[jp]);
                ldm_b(tBl, wn + jp * 16, ks, lane, bl[jp]);
            }
#pragma unroll
            for (int i = 0; i < 4; i++)
#pragma unroll
                for (int j = 0; j < 4; j++) {
                    const uint32_t* ph = &bh[j >> 1][(j & 1) * 2];
                    const uint32_t* pl = &bl[j >> 1][(j & 1) * 2];
                    mma16816(d[i][j], ah[i], ph);
                    mma16816(d[i][j], ah[i], pl);
                    mma16816(d[i][j], al[i], ph);
                }
        }
    }
}

// ---------------------------------------------------------------------------
// Fused QKV projection. Q/K -> bf16 hi/lo; V -> fp16 single (for fp16 PV).
// ---------------------------------------------------------------------------
__global__ __launch_bounds__(256) void gemm_qkv(
    const __nv_bfloat16* __restrict__ Ahi, const __nv_bfloat16* __restrict__ Alo,
    const __nv_bfloat16* __restrict__ Whi, const __nv_bfloat16* __restrict__ Wlo,
    __nv_bfloat16* __restrict__ Qhi, __nv_bfloat16* __restrict__ Qlo,
    __nv_bfloat16* __restrict__ Khi, __nv_bfloat16* __restrict__ Klo,
    __nv_bfloat16* __restrict__ Vhi)
{
    extern __shared__ __align__(1024) char smem[];
    const uint32_t sb = smem_u32(smem);

    const int t     = threadIdx.x;
    const int lane  = t & 31;
    const int w     = t >> 5;
    const int wm    = (w >> 2) * 64;
    const int wn    = (w & 3) * 32;
    const int which = blockIdx.x >> 3;
    const int bn    = (blockIdx.x & 7) * 128;
    const int bm    = blockIdx.y * 128;

    const __nv_bfloat16* Bhi = Whi + (size_t)which * (D_ * D_);
    const __nv_bfloat16* Blo = Wlo + (size_t)which * (D_ * D_);

    float d[4][4][4];
#pragma unroll
    for (int i = 0; i < 4; i++)
#pragma unroll
        for (int j = 0; j < 4; j++)
#pragma unroll
            for (int e = 0; e < 4; e++) d[i][j][e] = 0.0f;

    gemm_mainloop(Ahi, Alo, Bhi, Blo, sb, bm, bn, t, lane, wm, wn, d);

    if (which == 2) {
        // V: fp16 single
#pragma unroll
        for (int i = 0; i < 4; i++) {
            const int row = bm + wm + i * 16 + (lane >> 2);
#pragma unroll
            for (int j = 0; j < 4; j++) {
                const int col = bn + wn + j * 8 + (lane & 3) * 2;
                *(uint32_t*)(Vhi + (size_t)row * D_ + col)       = pack_f16x2(d[i][j][0], d[i][j][1]);
                *(uint32_t*)(Vhi + (size_t)(row + 8) * D_ + col) = pack_f16x2(d[i][j][2], d[i][j][3]);
            }
        }
    } else {
        __nv_bfloat16* Chi = (which == 0) ? Qhi : Khi;
        __nv_bfloat16* Clo = (which == 0) ? Qlo : Klo;
        const float scale = (which == 0) ? 0.125f : 1.0f;
#pragma unroll
        for (int i = 0; i < 4; i++) {
            const int row = bm + wm + i * 16 + (lane >> 2);
#pragma unroll
            for (int j = 0; j < 4; j++) {
                const int col = bn + wn + j * 8 + (lane & 3) * 2;
                uint32_t h01, l01, h23, l23;
                pack_hilo(d[i][j][0] * scale, d[i][j][1] * scale, h01, l01);
                pack_hilo(d[i][j][2] * scale, d[i][j][3] * scale, h23, l23);
                *(uint32_t*)(Chi + (size_t)row * D_ + col)       = h01;
                *(uint32_t*)(Clo + (size_t)row * D_ + col)       = l01;
                *(uint32_t*)(Chi + (size_t)(row + 8) * D_ + col) = h23;
                *(uint32_t*)(Clo + (size_t)(row + 8) * D_ + col) = l23;
            }
        }
    }
}

// ---------------------------------------------------------------------------
// O-projection GEMM (fp32 output)
// ---------------------------------------------------------------------------
__global__ __launch_bounds__(256) void gemm_out(
    const __nv_bfloat16* __restrict__ Ahi, const __nv_bfloat16* __restrict__ Alo,
    const __nv_bfloat16* __restrict__ Bhi, const __nv_bfloat16* __restrict__ Blo,
    float* __restrict__ C)
{
    extern __shared__ __align__(1024) char smem[];
    const uint32_t sb = smem_u32(smem);

    const int t    = threadIdx.x;
    const int lane = t & 31;
    const int w    = t >> 5;
    const int wm   = (w >> 2) * 64;
    const int wn   = (w & 3) * 32;
    const int bm   = blockIdx.y * 128;
    const int bn   = blockIdx.x * 128;

    float d[4][4][4];
#pragma unroll
    for (int i = 0; i < 4; i++)
#pragma unroll
        for (int j = 0; j < 4; j++)
#pragma unroll
            for (int e = 0; e < 4; e++) d[i][j][e] = 0.0f;

    gemm_mainloop(Ahi, Alo, Bhi, Blo, sb, bm, bn, t, lane, wm, wn, d);

#pragma unroll
    for (int i = 0; i < 4; i++) {
        const int row = bm + wm + i * 16 + (lane >> 2);
#pragma unroll
        for (int j = 0; j < 4; j++) {
            const int col = bn + wn + j * 8 + (lane & 3) * 2;
            *(float2*)(C + (size_t)row * D_ + col)       = make_float2(d[i][j][0], d[i][j][1]);
            *(float2*)(C + (size_t)(row + 8) * D_ + col) = make_float2(d[i][j][2], d[i][j][3]);
        }
    }
}

// ---------------------------------------------------------------------------
// Flash attention — q64, stage = Khi/Klo bf16 + V fp16 = 24KB; 2 stages = 48KB.
// Q recycled into stage0 after prologue. kv(kt) in stage (kt+1)&1.
// QK: bf16x3. PV: fp16 single product (P cvt f32->f16x2).
// ---------------------------------------------------------------------------
#define ATT_STAGE 24576
#define ATT_SMEM  (2 * ATT_STAGE)

__global__ __launch_bounds__(128, 3) void attn_mma(
    const __nv_bfloat16* __restrict__ Qhi, const __nv_bfloat16* __restrict__ Qlo,
    const __nv_bfloat16* __restrict__ Khi, const __nv_bfloat16* __restrict__ Klo,
    const __nv_bfloat16* __restrict__ Vh_g,
    __nv_bfloat16* __restrict__ AOhi, __nv_bfloat16* __restrict__ AOlo)
{
    extern __shared__ __align__(1024) char smem[];
    const uint32_t sb = smem_u32(smem);
    const int qt   = (int)gridDim.x - 1 - (int)blockIdx.x;
    const int h    = blockIdx.y;
    const int b    = blockIdx.z;
    const int tid  = threadIdx.x;
    const int lane = tid & 31;
    const int w    = tid >> 5;

    const size_t rowbase = (size_t)b * S_;
    const size_t cb      = (size_t)h * DK_;
    const int    q0      = qt * 64;

    // Q -> stage0 Kh/Kl region (Qhi at +0, Qlo at +8192); kv0 -> stage1
#pragma unroll
    for (int i = 0; i < 4; i++) {
        int p = tid + 128 * i; int r = p >> 3, ck = p & 7;
        size_t g = (rowbase + q0 + r) * D_ + cb + ck * 8;
        uint32_t so = swoff128(r, ck);
        CP_ASYNC_16(sb + so,        Qhi + g);
        CP_ASYNC_16(sb + 8192 + so, Qlo + g);
    }
    CP_COMMIT();

    auto load_kv = [&](int kt, int st) {
        uint32_t s = sb + (uint32_t)st * ATT_STAGE;
#pragma unroll
        for (int i = 0; i < 4; i++) {
            int p = tid + 128 * i; int r = p >> 3, ck = p & 7;
            uint32_t so = swoff128(r, ck);
            size_t g = (rowbase + kt * 64 + r) * D_ + cb + ck * 8;
            CP_ASYNC_16(s + so,         Khi + g);
            CP_ASYNC_16(s + 8192  + so, Klo + g);
            CP_ASYNC_16(s + 16384 + so, Vh_g + g);
        }
        CP_COMMIT();
    };
    load_kv(0, 1);

    cp_wait<1>();          // Q group complete
    __syncthreads();

    uint32_t qh[4][4], ql[4][4];
#pragma unroll
    for (int t4 = 0; t4 < 4; t4++) {
        ldm_a128(sb,        w * 16, t4, lane, qh[t4]);
        ldm_a128(sb + 8192, w * 16, t4, lane, ql[t4]);
    }
    __syncthreads();       // all warps done reading Q before stage0 reuse

    float o[8][4];
#pragma unroll
    for (int j = 0; j < 8; j++)
#pragma unroll
        for (int e = 0; e < 4; e++) o[j][e] = 0.0f;
    float miA = -INFINITY, miB = -INFINITY, liA = 0.0f, liB = 0.0f;

    const int rA = w * 16 + (lane >> 2);
    const int cl = 2 * (lane & 3);

    for (int kt = 0; kt <= qt; kt++) {
        if (kt < qt) { load_kv(kt + 1, kt & 1); cp_wait<1>(); }
        else         { cp_wait<0>(); }
        __syncthreads();

        const uint32_t Kh = sb + (uint32_t)((kt + 1) & 1) * ATT_STAGE;
        const uint32_t Kl = Kh + 8192, Vh = Kh + 16384;

        float s[8][4];
#pragma unroll
        for (int j = 0; j < 8; j++)
#pragma unroll
            for (int e = 0; e < 4; e++) s[j][e] = 0.0f;

#pragma unroll
        for (int t4 = 0; t4 < 4; t4++) {
#pragma unroll
            for (int jp = 0; jp < 4; jp++) {
                uint32_t kh[4], kl[4];
                ldm_b128(Kh, jp * 16, t4, lane, kh);
                ldm_b128(Kl, jp * 16, t4, lane, kl);
                mma16816(s[2 * jp],     qh[t4], kh);
                mma16816(s[2 * jp],     qh[t4], kl);
                mma16816(s[2 * jp],     ql[t4], kh);
                mma16816(s[2 * jp + 1], qh[t4], kh + 2);
                mma16816(s[2 * jp + 1], qh[t4], kl + 2);
                mma16816(s[2 * jp + 1], ql[t4], kh + 2);
            }
        }

        if (kt == qt) {
#pragma unroll
            for (int j = 0; j < 8; j++) {
                int c = 8 * j + cl;
                if (c     > rA)     s[j][0] = -INFINITY;
                if (c + 1 > rA)     s[j][1] = -INFINITY;
                if (c     > rA + 8) s[j][2] = -INFINITY;
                if (c + 1 > rA + 8) s[j][3] = -INFINITY;
            }
        }

        float mxA = s[0][0], mxB = s[0][2];
#pragma unroll
        for (int j = 0; j < 8; j++) {
            mxA = fmaxf(mxA, fmaxf(s[j][0], s[j][1]));
            mxB = fmaxf(mxB, fmaxf(s[j][2], s[j][3]));
        }
        mxA = fmaxf(mxA, __shfl_xor_sync(0xffffffffu, mxA, 1));
        mxA = fmaxf(mxA, __shfl_xor_sync(0xffffffffu, mxA, 2));
        mxB = fmaxf(mxB, __shfl_xor_sync(0xffffffffu, mxB, 1));
        mxB = fmaxf(mxB, __shfl_xor_sync(0xffffffffu, mxB, 2));

        float nA = fmaxf(miA, mxA), nB = fmaxf(miB, mxB);
        float aA = __expf(miA - nA), aB = __expf(miB - nB);
        miA = nA; miB = nB;
        liA *= aA; liB *= aB;
#pragma unroll
        for (int j = 0; j < 8; j++) {
            s[j][0] = __expf(s[j][0] - miA);
            s[j][1] = __expf(s[j][1] - miA);
            s[j][2] = __expf(s[j][2] - miB);
            s[j][3] = __expf(s[j][3] - miB);
            liA += s[j][0] + s[j][1];
            liB += s[j][2] + s[j][3];
            o[j][0] *= aA; o[j][1] *= aA; o[j][2] *= aB; o[j][3] *= aB;
        }

        // P fragments as fp16x2 (A-frag layout == C-frag layout)
        uint32_t ph[4][4];
#pragma unroll
        for (int t4 = 0; t4 < 4; t4++) {
            ph[t4][0] = pack_f16x2(s[2 * t4][0],     s[2 * t4][1]);
            ph[t4][1] = pack_f16x2(s[2 * t4][2],     s[2 * t4][3]);
            ph[t4][2] = pack_f16x2(s[2 * t4 + 1][0], s[2 * t4 + 1][1]);
            ph[t4][3] = pack_f16x2(s[2 * t4 + 1][2], s[2 * t4 + 1][3]);
        }

        // O += P V  (fp16 single product)
#pragma unroll
        for (int t4 = 0; t4 < 4; t4++) {
#pragma unroll
            for (int jp = 0; jp < 4; jp++) {
                uint32_t vh[4];
                ldm_vt128(Vh, t4 * 16, jp, lane, vh);
                mma16816f16(o[2 * jp],     ph[t4], vh);
                mma16816f16(o[2 * jp + 1], ph[t4], vh + 2);
            }
        }
        __syncthreads();   // stage fully consumed before refill
    }

    liA += __shfl_xor_sync(0xffffffffu, liA, 1);
    liA += __shfl_xor_sync(0xffffffffu, liA, 2);
    liB += __shfl_xor_sync(0xffffffffu, liB, 1);
    liB += __shfl_xor_sync(0xffffffffu, liB, 2);
    const float invA = 1.0f / liA, invB = 1.0f / liB;

    const size_t gA = (rowbase + q0 + rA) * D_ + cb + cl;
#pragma unroll
    for (int j = 0; j < 8; j++) {
        uint32_t hA, lA, hB, lB;
        pack_hilo(o[j][0] * invA, o[j][1] * invA, hA, lA);
        pack_hilo(o[j][2] * invB, o[j][3] * invB, hB, lB);
        *(uint32_t*)(AOhi + gA + 8 * j)           = hA;
        *(uint32_t*)(AOlo + gA + 8 * j)           = lA;
        *(uint32_t*)(AOhi + gA + 8 * j + 8 * D_)  = hB;
        *(uint32_t*)(AOlo + gA + 8 * j + 8 * D_)  = lB;
    }
}

// ---------------------------------------------------------------------------
// kernel_launch
// ---------------------------------------------------------------------------
extern "C" void kernel_launch(void* const* d_in, const int* in_sizes, int n_in,
                              void* d_out, int out_size)
{
    const float* x  = (const float*)d_in[0];
    const float* wp[4] = { (const float*)d_in[1], (const float*)d_in[2],
                           (const float*)d_in[3], (const float*)d_in[4] };
    float* out = (float*)d_out;

    __nv_bfloat16 *xhi, *xlo, *qhi, *qlo, *khi, *klo, *vhi, *aohi, *aolo, *whi, *wlo;
    cudaGetSymbolAddress((void**)&xhi,  g_xhi);
    cudaGetSymbolAddress((void**)&xlo,  g_xlo);
    cudaGetSymbolAddress((void**)&qhi,  g_qhi);
    cudaGetSymbolAddress((void**)&qlo,  g_qlo);
    cudaGetSymbolAddress((void**)&khi,  g_khi);
    cudaGetSymbolAddress((void**)&klo,  g_klo);
    cudaGetSymbolAddress((void**)&vhi,  g_vhi);
    cudaGetSymbolAddress((void**)&aohi, g_aohi);
    cudaGetSymbolAddress((void**)&aolo, g_aolo);
    cudaGetSymbolAddress((void**)&whi,  g_whi);
    cudaGetSymbolAddress((void**)&wlo,  g_wlo);

    const int n2x = M_ * D_ / 2;
    const int n2w = D_ * D_ / 2;
    f32_to_hilo<<<(n2x + 255) / 256, 256>>>(x, xhi, xlo, n2x);
    w4_to_hilo<<<dim3((n2w + 255) / 256, 4), 256>>>(wp[0], wp[1], wp[2], wp[3], whi, wlo);

    cudaFuncSetAttribute(gemm_qkv, cudaFuncAttributeMaxDynamicSharedMemorySize, GEMM_SMEM);
    cudaFuncSetAttribute(gemm_out, cudaFuncAttributeMaxDynamicSharedMemorySize, GEMM_SMEM);
    cudaFuncSetAttribute(attn_mma, cudaFuncAttributeMaxDynamicSharedMemorySize, ATT_SMEM);

    gemm_qkv<<<dim3(24, M_ / 128), 256, GEMM_SMEM>>>(xhi, xlo, whi, wlo,
                                                     qhi, qlo, khi, klo, vhi);

    attn_mma<<<dim3(S_ / 64, H_, B_), 128, ATT_SMEM>>>(qhi, qlo, khi, klo, vhi, aohi, aolo);

    gemm_out<<<dim3(D_ / 128, M_ / 128), 256, GEMM_SMEM>>>(
        aohi, aolo, whi + 3 * (size_t)(D_ * D_), wlo + 3 * (size_t)(D_ * D_), out);
}

// round 17
// speedup vs baseline: 1.2252x; 1.0676x over previous
// R17: third submission of the R15 source (broker container failures on R15 &
// R16, 4 attempts; audit clean both times; R12-source precedent passed on its
// 3rd round). Last retry before structural fallback.
// R15: O-projection path -> f16 2-product (AO stored f16 single by attn
// epilogue; W_o split f16 hi/lo; gemm_out does a*wh + a*wl). Q/K/V + attn
// core byte-identical to R14 (807us, rel_err 2.45e-4).
#include <cuda_runtime.h>
#include <cuda_bf16.h>
#include <cuda_fp16.h>
#include <math.h>
#include <stdint.h>

#define B_  4
#define S_  2048
#define D_  1024
#define H_  16
#define DK_ 64
#define M_  (B_ * S_)

// ---------------------------------------------------------------------------
// Scratch (16-bit buffers; payload format noted per buffer)
// ---------------------------------------------------------------------------
__device__ __nv_bfloat16 g_xhi [M_ * D_];
__device__ __nv_bfloat16 g_xlo [M_ * D_];
__device__ __nv_bfloat16 g_qhi [M_ * D_];
__device__ __nv_bfloat16 g_qlo [M_ * D_];
__device__ __nv_bfloat16 g_khi [M_ * D_];
__device__ __nv_bfloat16 g_klo [M_ * D_];
__device__ __nv_bfloat16 g_vhi [M_ * D_];          // fp16 payload
__device__ __nv_bfloat16 g_aof [M_ * D_];          // fp16 payload (attn out)
__device__ __nv_bfloat16 g_whi [4][D_ * D_];       // w0..w2 bf16-hi, w3 f16-hi
__device__ __nv_bfloat16 g_wlo [4][D_ * D_];       // w0..w2 bf16-lo, w3 f16-lo

// ---------------------------------------------------------------------------
// PTX helpers
// ---------------------------------------------------------------------------
__device__ __forceinline__ uint32_t smem_u32(const void* p) {
    uint32_t a;
    asm("{ .reg .u64 t; cvta.to.shared.u64 t, %1; cvt.u32.u64 %0, t; }" : "=r"(a) : "l"(p));
    return a;
}

#define CP_ASYNC_16(sa, gp) \
    asm volatile("cp.async.cg.shared.global [%0], [%1], 16;" :: "r"(sa), "l"(gp))
#define CP_COMMIT() asm volatile("cp.async.commit_group;" ::: "memory")
template<int N> __device__ __forceinline__ void cp_wait() {
    asm volatile("cp.async.wait_group %0;" :: "n"(N) : "memory");
}

__device__ __forceinline__ void mma16816(float* d, const uint32_t* a, const uint32_t* b) {
    asm volatile("mma.sync.aligned.m16n8k16.row.col.f32.bf16.bf16.f32 "
                 "{%0,%1,%2,%3}, {%4,%5,%6,%7}, {%8,%9}, {%0,%1,%2,%3};"
                 : "+f"(d[0]), "+f"(d[1]), "+f"(d[2]), "+f"(d[3])
                 : "r"(a[0]), "r"(a[1]), "r"(a[2]), "r"(a[3]), "r"(b[0]), "r"(b[1]));
}
__device__ __forceinline__ void mma16816f16(float* d, const uint32_t* a, const uint32_t* b) {
    asm volatile("mma.sync.aligned.m16n8k16.row.col.f32.f16.f16.f32 "
                 "{%0,%1,%2,%3}, {%4,%5,%6,%7}, {%8,%9}, {%0,%1,%2,%3};"
                 : "+f"(d[0]), "+f"(d[1]), "+f"(d[2]), "+f"(d[3])
                 : "r"(a[0]), "r"(a[1]), "r"(a[2]), "r"(a[3]), "r"(b[0]), "r"(b[1]));
}

// fp32 pair -> bf16x2 hi + exact residual bf16x2 lo. a = even col, b = odd col.
__device__ __forceinline__ void pack_hilo(float a, float b, uint32_t& hi, uint32_t& lo) {
    uint32_t h;
    asm("cvt.rn.bf16x2.f32 %0, %1, %2;" : "=r"(h) : "f"(b), "f"(a));
    float ra = a - __uint_as_float(h << 16);
    float rb = b - __uint_as_float(h & 0xffff0000u);
    uint32_t l;
    asm("cvt.rn.bf16x2.f32 %0, %1, %2;" : "=r"(l) : "f"(rb), "f"(ra));
    hi = h; lo = l;
}
// fp32 pair -> f16x2 (a low half, b high half)
__device__ __forceinline__ uint32_t pack_f16x2(float a, float b) {
    uint32_t h;
    asm("cvt.rn.f16x2.f32 %0, %1, %2;" : "=r"(h) : "f"(b), "f"(a));
    return h;
}
// fp32 pair -> f16x2 hi + residual f16x2 lo
__device__ __forceinline__ void pack_f16_hilo(float a, float b, uint32_t& hi, uint32_t& lo) {
    uint32_t h = pack_f16x2(a, b);
    __half2 h2 = *reinterpret_cast<__half2*>(&h);
    float ra = a - __low2float(h2);
    float rb = b - __high2float(h2);
    lo = pack_f16x2(ra, rb);
    hi = h;
}

// ----- 64B-row tiles (GEMM, BK=32) -----
__device__ __forceinline__ uint32_t sw_off(int row, int chunk) {
    return (uint32_t)(row * 64 + ((chunk ^ ((row >> 1) & 3)) << 4));
}
__device__ __forceinline__ void ldm_a(uint32_t tile, int row0, int kstep, int lane, uint32_t* r) {
    int row = row0 + (lane & 15);
    int ck  = kstep * 2 + ((lane >> 4) & 1);
    uint32_t addr = tile + sw_off(row, ck);
    asm volatile("ldmatrix.sync.aligned.m8n8.x4.shared.b16 {%0,%1,%2,%3}, [%4];"
                 : "=r"(r[0]), "=r"(r[1]), "=r"(r[2]), "=r"(r[3]) : "r"(addr));
}
__device__ __forceinline__ void ldm_b(uint32_t tile, int row0, int kstep, int lane, uint32_t* r) {
    int row = row0 + (lane & 7) + ((lane & 16) ? 8 : 0);
    int ck  = kstep * 2 + ((lane >> 3) & 1);
    uint32_t addr = tile + sw_off(row, ck);
    asm volatile("ldmatrix.sync.aligned.m8n8.x4.shared.b16 {%0,%1,%2,%3}, [%4];"
                 : "=r"(r[0]), "=r"(r[1]), "=r"(r[2]), "=r"(r[3]) : "r"(addr));
}

// ----- 128B-row tiles (attention, 64x64 16-bit) -----
__device__ __forceinline__ uint32_t swoff128(int row, int ck) {
    return (uint32_t)(row * 128 + ((ck ^ (row & 7)) << 4));
}
__device__ __forceinline__ void ldm_a128(uint32_t tile, int row0, int t4, int lane, uint32_t* r) {
    int row = row0 + (lane & 15);
    int ck  = t4 * 2 + ((lane >> 4) & 1);
    uint32_t addr = tile + swoff128(row, ck);
    asm volatile("ldmatrix.sync.aligned.m8n8.x4.shared.b16 {%0,%1,%2,%3}, [%4];"
                 : "=r"(r[0]), "=r"(r[1]), "=r"(r[2]), "=r"(r[3]) : "r"(addr));
}
__device__ __forceinline__ void ldm_b128(uint32_t tile, int n0, int t4, int lane, uint32_t* r) {
    int row = n0 + (lane & 7) + ((lane >> 1) & 8);
    int ck  = t4 * 2 + ((lane >> 3) & 1);
    uint32_t addr = tile + swoff128(row, ck);
    asm volatile("ldmatrix.sync.aligned.m8n8.x4.shared.b16 {%0,%1,%2,%3}, [%4];"
                 : "=r"(r[0]), "=r"(r[1]), "=r"(r[2]), "=r"(r[3]) : "r"(addr));
}
__device__ __forceinline__ void ldm_vt128(uint32_t tile, int k0, int jp, int lane, uint32_t* r) {
    int row = k0 + (lane & 7) + (lane & 8);
    int ck  = jp * 2 + ((lane >> 4) & 1);
    uint32_t addr = tile + swoff128(row, ck);
    asm volatile("ldmatrix.sync.aligned.m8n8.x4.trans.shared.b16 {%0,%1,%2,%3}, [%4];"
                 : "=r"(r[0]), "=r"(r[1]), "=r"(r[2]), "=r"(r[3]) : "r"(addr));
}

// ---------------------------------------------------------------------------
// converts
// ---------------------------------------------------------------------------
__global__ __launch_bounds__(256) void f32_to_hilo(const float* __restrict__ in,
                                                   __nv_bfloat16* __restrict__ hi,
                                                   __nv_bfloat16* __restrict__ lo,
                                                   int n2)
{
    int i = blockIdx.x * blockDim.x + threadIdx.x;
    if (i >= n2) return;
    float2 v = ((const float2*)in)[i];
    uint32_t h, l;
    pack_hilo(v.x, v.y, h, l);
    ((uint32_t*)hi)[i] = h;
    ((uint32_t*)lo)[i] = l;
}

// w0..w2: bf16 hi/lo.  w3 (W_o): f16 hi/lo.
__global__ __launch_bounds__(256) void w4_to_hilo(const float* __restrict__ w0,
                                                  const float* __restrict__ w1,
                                                  const float* __restrict__ w2,
                                                  const float* __restrict__ w3,
                                                  __nv_bfloat16* __restrict__ hi,
                                                  __nv_bfloat16* __restrict__ lo)
{
    const int n2 = D_ * D_ / 2;
    int i = blockIdx.x * blockDim.x + threadIdx.x;
    if (i >= n2) return;
    const int which = blockIdx.y;
    const float* src = (which == 0) ? w0 : (which == 1) ? w1 : (which == 2) ? w2 : w3;
    float2 v = ((const float2*)src)[i];
    uint32_t h, l;
    if (which == 3) pack_f16_hilo(v.x, v.y, h, l);
    else            pack_hilo(v.x, v.y, h, l);
    ((uint32_t*)(hi + (size_t)which * (D_ * D_)))[i] = h;
    ((uint32_t*)(lo + (size_t)which * (D_ * D_)))[i] = l;
}

// ---------------------------------------------------------------------------
// Shared GEMM mainloop — bf16x3, 3-stage cp.async (unchanged, QKV only)
// ---------------------------------------------------------------------------
#define STAGE_B   32768
#define GEMM_SMEM (3 * STAGE_B)
#define NCHUNK    32

__device__ __forceinline__ void gemm_mainloop(
    const __nv_bfloat16* __restrict__ Ahi, const __nv_bfloat16* __restrict__ Alo,
    const __nv_bfloat16* __restrict__ Bhi, const __nv_bfloat16* __restrict__ Blo,
    uint32_t sb, int bm, int bn, int t, int lane, int wm, int wn,
    float d[4][4][4])
{
    const int r0 = t >> 2,         c0 = t & 3;
    const int r1 = (t + 256) >> 2, c1 = t & 3;

    auto load_chunk = [&](int chunk, int st) {
        const size_t kb = (size_t)chunk * 32;
        const uint32_t s = sb + (uint32_t)st * STAGE_B;
        {
            uint32_t so = sw_off(r0, c0);
            const size_t ga = (size_t)(bm + r0) * D_ + kb + c0 * 8;
            const size_t gb = (size_t)(bn + r0) * D_ + kb + c0 * 8;
            CP_ASYNC_16(s + so,         Ahi + ga);
            CP_ASYNC_16(s + 8192  + so, Alo + ga);
            CP_ASYNC_16(s + 16384 + so, Bhi + gb);
            CP_ASYNC_16(s + 24576 + so, Blo + gb);
        }
        {
            uint32_t so = sw_off(r1, c1);
            const size_t ga = (size_t)(bm + r1) * D_ + kb + c1 * 8;
            const size_t gb = (size_t)(bn + r1) * D_ + kb + c1 * 8;
            CP_ASYNC_16(s + so,         Ahi + ga);
            CP_ASYNC_16(s + 8192  + so, Alo + ga);
            CP_ASYNC_16(s + 16384 + so, Bhi + gb);
            CP_ASYNC_16(s + 24576 + so, Blo + gb);
        }
        CP_COMMIT();
    };

    load_chunk(0, 0);
    load_chunk(1, 1);

    for (int chunk = 0; chunk < NCHUNK; chunk++) {
        if (chunk + 2 < NCHUNK) cp_wait<1>();
        else                    cp_wait<0>();
        __syncthreads();
        if (chunk + 2 < NCHUNK) load_chunk(chunk + 2, (chunk + 2) % 3);

        const uint32_t tAh = sb + (uint32_t)(chunk % 3) * STAGE_B;
        const uint32_t tAl = tAh + 8192;
        const uint32_t tBh = tAh + 16384;
        const uint32_t tBl = tAh + 24576;

#pragma unroll
        for (int ks = 0; ks < 2; ks++) {
            uint32_t ah[4][4], al[4][4];
#pragma unroll
            for (int i = 0; i < 4; i++) {
                ldm_a(tAh, wm + i * 16, ks, lane, ah[i]);
                ldm_a(tAl, wm + i * 16, ks, lane, al[i]);
            }
            uint32_t bh[2][4], bl[2][4];
#pragma unroll
            for (int jp = 0; jp < 2; jp++) {
                ldm_b(tBh, wn + jp * 16, ks, lane, bh[jp]);
                ldm_b(tBl, wn + jp * 16, ks, lane, bl[jp]);
            }
#pragma unroll
            for (int i = 0; i < 4; i++)
#pragma unroll
                for (int j = 0; j < 4; j++) {
                    const uint32_t* ph = &bh[j >> 1][(j & 1) * 2];
                    const uint32_t* pl = &bl[j >> 1][(j & 1) * 2];
                    mma16816(d[i][j], ah[i], ph);
                    mma16816(d[i][j], ah[i], pl);
                    mma16816(d[i][j], al[i], ph);
                }
        }
    }
}

// ---------------------------------------------------------------------------
// Fused QKV projection (unchanged from R14)
// ---------------------------------------------------------------------------
__global__ __launch_bounds__(256) void gemm_qkv(
    const __nv_bfloat16* __restrict__ Ahi, const __nv_bfloat16* __restrict__ Alo,
    const __nv_bfloat16* __restrict__ Whi, const __nv_bfloat16* __restrict__ Wlo,
    __nv_bfloat16* __restrict__ Qhi, __nv_bfloat16* __restrict__ Qlo,
    __nv_bfloat16* __restrict__ Khi, __nv_bfloat16* __restrict__ Klo,
    __nv_bfloat16* __restrict__ Vhi)
{
    extern __shared__ __align__(1024) char smem[];
    const uint32_t sb = smem_u32(smem);

    const int t     = threadIdx.x;
    const int lane  = t & 31;
    const int w     = t >> 5;
    const int wm    = (w >> 2) * 64;
    const int wn    = (w & 3) * 32;
    const int which = blockIdx.x >> 3;
    const int bn    = (blockIdx.x & 7) * 128;
    const int bm    = blockIdx.y * 128;

    const __nv_bfloat16* Bhi = Whi + (size_t)which * (D_ * D_);
    const __nv_bfloat16* Blo = Wlo + (size_t)which * (D_ * D_);

    float d[4][4][4];
#pragma unroll
    for (int i = 0; i < 4; i++)
#pragma unroll
        for (int j = 0; j < 4; j++)
#pragma unroll
            for (int e = 0; e < 4; e++) d[i][j][e] = 0.0f;

    gemm_mainloop(Ahi, Alo, Bhi, Blo, sb, bm, bn, t, lane, wm, wn, d);

    if (which == 2) {
#pragma unroll
        for (int i = 0; i < 4; i++) {
            const int row = bm + wm + i * 16 + (lane >> 2);
#pragma unroll
            for (int j = 0; j < 4; j++) {
                const int col = bn + wn + j * 8 + (lane & 3) * 2;
                *(uint32_t*)(Vhi + (size_t)row * D_ + col)       = pack_f16x2(d[i][j][0], d[i][j][1]);
                *(uint32_t*)(Vhi + (size_t)(row + 8) * D_ + col) = pack_f16x2(d[i][j][2], d[i][j][3]);
            }
        }
    } else {
        __nv_bfloat16* Chi = (which == 0) ? Qhi : Khi;
        __nv_bfloat16* Clo = (which == 0) ? Qlo : Klo;
        const float scale = (which == 0) ? 0.125f : 1.0f;
#pragma unroll
        for (int i = 0; i < 4; i++) {
            const int row = bm + wm + i * 16 + (lane >> 2);
#pragma unroll
            for (int j = 0; j < 4; j++) {
                const int col = bn + wn + j * 8 + (lane & 3) * 2;
                uint32_t h01, l01, h23, l23;
                pack_hilo(d[i][j][0] * scale, d[i][j][1] * scale, h01, l01);
                pack_hilo(d[i][j][2] * scale, d[i][j][3] * scale, h23, l23);
                *(uint32_t*)(Chi + (size_t)row * D_ + col)       = h01;
                *(uint32_t*)(Clo + (size_t)row * D_ + col)       = l01;
                *(uint32_t*)(Chi + (size_t)(row + 8) * D_ + col) = h23;
                *(uint32_t*)(Clo + (size_t)(row + 8) * D_ + col) = l23;
            }
        }
    }
}

// ---------------------------------------------------------------------------
// O-projection GEMM — f16 2-product: C = A_f16 * (Wh + Wl), fp32 accum.
// Stage: A(8K) + Bh(8K) + Bl(8K) = 24KB; 3 stages = 72KB.
// ---------------------------------------------------------------------------
#define OSTAGE_B   24576
#define OGEMM_SMEM (3 * OSTAGE_B)

__global__ __launch_bounds__(256) void gemm_out(
    const __nv_bfloat16* __restrict__ Af16,
    const __nv_bfloat16* __restrict__ Bhi, const __nv_bfloat16* __restrict__ Blo,
    float* __restrict__ C)
{
    extern __shared__ __align__(1024) char smem[];
    const uint32_t sb = smem_u32(smem);

    const int t    = threadIdx.x;
    const int lane = t & 31;
    const int w    = t >> 5;
    const int wm   = (w >> 2) * 64;
    const int wn   = (w & 3) * 32;
    const int bm   = blockIdx.y * 128;
    const int bn   = blockIdx.x * 128;

    const int r0 = t >> 2,         c0 = t & 3;
    const int r1 = (t + 256) >> 2, c1 = t & 3;

    auto load_chunk = [&](int chunk, int st) {
        const size_t kb = (size_t)chunk * 32;
        const uint32_t s = sb + (uint32_t)st * OSTAGE_B;
        {
            uint32_t so = sw_off(r0, c0);
            const size_t ga = (size_t)(bm + r0) * D_ + kb + c0 * 8;
            const size_t gb = (size_t)(bn + r0) * D_ + kb + c0 * 8;
            CP_ASYNC_16(s + so,         Af16 + ga);
            CP_ASYNC_16(s + 8192  + so, Bhi + gb);
            CP_ASYNC_16(s + 16384 + so, Blo + gb);
        }
        {
            uint32_t so = sw_off(r1, c1);
            const size_t ga = (size_t)(bm + r1) * D_ + kb + c1 * 8;
            const size_t gb = (size_t)(bn + r1) * D_ + kb + c1 * 8;
            CP_ASYNC_16(s + so,         Af16 + ga);
            CP_ASYNC_16(s + 8192  + so, Bhi + gb);
            CP_ASYNC_16(s + 16384 + so, Blo + gb);
        }
        CP_COMMIT();
    };

    float d[4][4][4];
#pragma unroll
    for (int i = 0; i < 4; i++)
#pragma unroll
        for (int j = 0; j < 4; j++)
#pragma unroll
            for (int e = 0; e < 4; e++) d[i][j][e] = 0.0f;

    load_chunk(0, 0);
    load_chunk(1, 1);

    for (int chunk = 0; chunk < NCHUNK; chunk++) {
        if (chunk + 2 < NCHUNK) cp_wait<1>();
        else                    cp_wait<0>();
        __syncthreads();
        if (chunk + 2 < NCHUNK) load_chunk(chunk + 2, (chunk + 2) % 3);

        const uint32_t tA  = sb + (uint32_t)(chunk % 3) * OSTAGE_B;
        const uint32_t tBh = tA + 8192;
        const uint32_t tBl = tA + 16384;

#pragma unroll
        for (int ks = 0; ks < 2; ks++) {
            uint32_t a[4][4];
#pragma unroll
            for (int i = 0; i < 4; i++)
                ldm_a(tA, wm + i * 16, ks, lane, a[i]);
            uint32_t bh[2][4], bl[2][4];
#pragma unroll
            for (int jp = 0; jp < 2; jp++) {
                ldm_b(tBh, wn + jp * 16, ks, lane, bh[jp]);
                ldm_b(tBl, wn + jp * 16, ks, lane, bl[jp]);
            }
#pragma unroll
            for (int i = 0; i < 4; i++)
#pragma unroll
                for (int j = 0; j < 4; j++) {
                    const uint32_t* ph = &bh[j >> 1][(j & 1) * 2];
                    const uint32_t* pl = &bl[j >> 1][(j & 1) * 2];
                    mma16816f16(d[i][j], a[i], ph);
                    mma16816f16(d[i][j], a[i], pl);
                }
        }
    }

#pragma unroll
    for (int i = 0; i < 4; i++) {
        const int row = bm + wm + i * 16 + (lane >> 2);
#pragma unroll
        for (int j = 0; j < 4; j++) {
            const int col = bn + wn + j * 8 + (lane & 3) * 2;
            *(float2*)(C + (size_t)row * D_ + col)       = make_float2(d[i][j][0], d[i][j][1]);
            *(float2*)(C + (size_t)(row + 8) * D_ + col) = make_float2(d[i][j][2], d[i][j][3]);
        }
    }
}

// ---------------------------------------------------------------------------
// Flash attention — R14 core; epilogue now emits AO as f16 single.
// ---------------------------------------------------------------------------
#define ATT_STAGE 24576
#define ATT_SMEM  (2 * ATT_STAGE)

__global__ __launch_bounds__(128, 3) void attn_mma(
    const __nv_bfloat16* __restrict__ Qhi, const __nv_bfloat16* __restrict__ Qlo,
    const __nv_bfloat16* __restrict__ Khi, const __nv_bfloat16* __restrict__ Klo,
    const __nv_bfloat16* __restrict__ Vh_g,
    __nv_bfloat16* __restrict__ AOf)
{
    extern __shared__ __align__(1024) char smem[];
    const uint32_t sb = smem_u32(smem);
    const int qt   = (int)gridDim.x - 1 - (int)blockIdx.x;
    const int h    = blockIdx.y;
    const int b    = blockIdx.z;
    const int tid  = threadIdx.x;
    const int lane = tid & 31;
    const int w    = tid >> 5;

    const size_t rowbase = (size_t)b * S_;
    const size_t cb      = (size_t)h * DK_;
    const int    q0      = qt * 64;

#pragma unroll
    for (int i = 0; i < 4; i++) {
        int p = tid + 128 * i; int r = p >> 3, ck = p & 7;
        size_t g = (rowbase + q0 + r) * D_ + cb + ck * 8;
        uint32_t so = swoff128(r, ck);
        CP_ASYNC_16(sb + so,        Qhi + g);
        CP_ASYNC_16(sb + 8192 + so, Qlo + g);
    }
    CP_COMMIT();

    auto load_kv = [&](int kt, int st) {
        uint32_t s = sb + (uint32_t)st * ATT_STAGE;
#pragma unroll
        for (int i = 0; i < 4; i++) {
            int p = tid + 128 * i; int r = p >> 3, ck = p & 7;
            uint32_t so = swoff128(r, ck);
            size_t g = (rowbase + kt * 64 + r) * D_ + cb + ck * 8;
            CP_ASYNC_16(s + so,         Khi + g);
            CP_ASYNC_16(s + 8192  + so, Klo + g);
            CP_ASYNC_16(s + 16384 + so, Vh_g + g);
        }
        CP_COMMIT();
    };
    load_kv(0, 1);

    cp_wait<1>();
    __syncthreads();

    uint32_t qh[4][4], ql[4][4];
#pragma unroll
    for (int t4 = 0; t4 < 4; t4++) {
        ldm_a128(sb,        w * 16, t4, lane, qh[t4]);
        ldm_a128(sb + 8192, w * 16, t4, lane, ql[t4]);
    }
    __syncthreads();

    float o[8][4];
#pragma unroll
    for (int j = 0; j < 8; j++)
#pragma unroll
        for (int e = 0; e < 4; e++) o[j][e] = 0.0f;
    float miA = -INFINITY, miB = -INFINITY, liA = 0.0f, liB = 0.0f;

    const int rA = w * 16 + (lane >> 2);
    const int cl = 2 * (lane & 3);

    for (int kt = 0; kt <= qt; kt++) {
        if (kt < qt) { load_kv(kt + 1, kt & 1); cp_wait<1>(); }
        else         { cp_wait<0>(); }
        __syncthreads();

        const uint32_t Kh = sb + (uint32_t)((kt + 1) & 1) * ATT_STAGE;
        const uint32_t Kl = Kh + 8192, Vh = Kh + 16384;

        float s[8][4];
#pragma unroll
        for (int j = 0; j < 8; j++)
#pragma unroll
            for (int e = 0; e < 4; e++) s[j][e] = 0.0f;

#pragma unroll
        for (int t4 = 0; t4 < 4; t4++) {
#pragma unroll
            for (int jp = 0; jp < 4; jp++) {
                uint32_t kh[4], kl[4];
                ldm_b128(Kh, jp * 16, t4, lane, kh);
                ldm_b128(Kl, jp * 16, t4, lane, kl);
                mma16816(s[2 * jp],     qh[t4], kh);
                mma16816(s[2 * jp],     qh[t4], kl);
                mma16816(s[2 * jp],     ql[t4], kh);
                mma16816(s[2 * jp + 1], qh[t4], kh + 2);
                mma16816(s[2 * jp + 1], qh[t4], kl + 2);
                mma16816(s[2 * jp + 1], ql[t4], kh + 2);
            }
        }

        if (kt == qt) {
#pragma unroll
            for (int j = 0; j < 8; j++) {
                int c = 8 * j + cl;
                if (c     > rA)     s[j][0] = -INFINITY;
                if (c + 1 > rA)     s[j][1] = -INFINITY;
                if (c     > rA + 8) s[j][2] = -INFINITY;
                if (c + 1 > rA + 8) s[j][3] = -INFINITY;
            }
        }

        float mxA = s[0][0], mxB = s[0][2];
#pragma unroll
        for (int j = 0; j < 8; j++) {
            mxA = fmaxf(mxA, fmaxf(s[j][0], s[j][1]));
            mxB = fmaxf(mxB, fmaxf(s[j][2], s[j][3]));
        }
        mxA = fmaxf(mxA, __shfl_xor_sync(0xffffffffu, mxA, 1));
        mxA = fmaxf(mxA, __shfl_xor_sync(0xffffffffu, mxA, 2));
        mxB = fmaxf(mxB, __shfl_xor_sync(0xffffffffu, mxB, 1));
        mxB = fmaxf(mxB, __shfl_xor_sync(0xffffffffu, mxB, 2));

        float nA = fmaxf(miA, mxA), nB = fmaxf(miB, mxB);
        float aA = __expf(miA - nA), aB = __expf(miB - nB);
        miA = nA; miB = nB;
        liA *= aA; liB *= aB;
#pragma unroll
        for (int j = 0; j < 8; j++) {
            s[j][0] = __expf(s[j][0] - miA);
            s[j][1] = __expf(s[j][1] - miA);
            s[j][2] = __expf(s[j][2] - miB);
            s[j][3] = __expf(s[j][3] - miB);
            liA += s[j][0] + s[j][1];
            liB += s[j][2] + s[j][3];
            o[j][0] *= aA; o[j][1] *= aA; o[j][2] *= aB; o[j][3] *= aB;
        }

        uint32_t ph[4][4];
#pragma unroll
        for (int t4 = 0; t4 < 4; t4++) {
            ph[t4][0] = pack_f16x2(s[2 * t4][0],     s[2 * t4][1]);
            ph[t4][1] = pack_f16x2(s[2 * t4][2],     s[2 * t4][3]);
            ph[t4][2] = pack_f16x2(s[2 * t4 + 1][0], s[2 * t4 + 1][1]);
            ph[t4][3] = pack_f16x2(s[2 * t4 + 1][2], s[2 * t4 + 1][3]);
        }

#pragma unroll
        for (int t4 = 0; t4 < 4; t4++) {
#pragma unroll
            for (int jp = 0; jp < 4; jp++) {
                uint32_t vh[4];
                ldm_vt128(Vh, t4 * 16, jp, lane, vh);
                mma16816f16(o[2 * jp],     ph[t4], vh);
                mma16816f16(o[2 * jp + 1], ph[t4], vh + 2);
            }
        }
        __syncthreads();
    }

    liA += __shfl_xor_sync(0xffffffffu, liA, 1);
    liA += __shfl_xor_sync(0xffffffffu, liA, 2);
    liB += __shfl_xor_sync(0xffffffffu, liB, 1);
    liB += __shfl_xor_sync(0xffffffffu, liB, 2);
    const float invA = 1.0f / liA, invB = 1.0f / liB;

    const size_t gA = (rowbase + q0 + rA) * D_ + cb + cl;
#pragma unroll
    for (int j = 0; j < 8; j++) {
        *(uint32_t*)(AOf + gA + 8 * j)          = pack_f16x2(o[j][0] * invA, o[j][1] * invA);
        *(uint32_t*)(AOf + gA + 8 * j + 8 * D_) = pack_f16x2(o[j][2] * invB, o[j][3] * invB);
    }
}

// ---------------------------------------------------------------------------
// kernel_launch
// ---------------------------------------------------------------------------
extern "C" void kernel_launch(void* const* d_in, const int* in_sizes, int n_in,
                              void* d_out, int out_size)
{
    const float* x  = (const float*)d_in[0];
    const float* wp[4] = { (const float*)d_in[1], (const float*)d_in[2],
                           (const float*)d_in[3], (const float*)d_in[4] };
    float* out = (float*)d_out;

    __nv_bfloat16 *xhi, *xlo, *qhi, *qlo, *khi, *klo, *vhi, *aof, *whi, *wlo;
    cudaGetSymbolAddress((void**)&xhi, g_xhi);
    cudaGetSymbolAddress((void**)&xlo, g_xlo);
    cudaGetSymbolAddress((void**)&qhi, g_qhi);
    cudaGetSymbolAddress((void**)&qlo, g_qlo);
    cudaGetSymbolAddress((void**)&khi, g_khi);
    cudaGetSymbolAddress((void**)&klo, g_klo);
    cudaGetSymbolAddress((void**)&vhi, g_vhi);
    cudaGetSymbolAddress((void**)&aof, g_aof);
    cudaGetSymbolAddress((void**)&whi, g_whi);
    cudaGetSymbolAddress((void**)&wlo, g_wlo);

    const int n2x = M_ * D_ / 2;
    const int n2w = D_ * D_ / 2;
    f32_to_hilo<<<(n2x + 255) / 256, 256>>>(x, xhi, xlo, n2x);
    w4_to_hilo<<<dim3((n2w + 255) / 256, 4), 256>>>(wp[0], wp[1], wp[2], wp[3], whi, wlo);

    cudaFuncSetAttribute(gemm_qkv, cudaFuncAttributeMaxDynamicSharedMemorySize, GEMM_SMEM);
    cudaFuncSetAttribute(gemm_out, cudaFuncAttributeMaxDynamicSharedMemorySize, OGEMM_SMEM);
    cudaFuncSetAttribute(attn_mma, cudaFuncAttributeMaxDynamicSharedMemorySize, ATT_SMEM);

    gemm_qkv<<<dim3(24, M_ / 128), 256, GEMM_SMEM>>>(xhi, xlo, whi, wlo,
                                                     qhi, qlo, khi, klo, vhi);

    attn_mma<<<dim3(S_ / 64, H_, B_), 128, ATT_SMEM>>>(qhi, qlo, khi, klo, vhi, aof);

    gemm_out<<<dim3(D_ / 128, M_ / 128), 256, OGEMM_SMEM>>>(
        aof, whi + 3 * (size_t)(D_ * D_), wlo + 3 * (size_t)(D_ * D_), out);
}